// round 3
// baseline (speedup 1.0000x reference)
#include <cuda_runtime.h>

#define NN 50000
#define EE 600000
#define DH 128
#define DO 40
#define BN_EPS 1e-5f

// ---------------- scratch (device globals; referenced by symbol only) -------
__device__ __align__(16) float g_h[(size_t)NN * DH];   // GEMM out / agg in
__device__ __align__(16) float g_a[(size_t)NN * DH];   // agg out / GEMM in
__device__ int   g_cnt[NN];
__device__ int   g_start[NN + 1];
__device__ int   g_cursor[NN];
__device__ int   g_srcCSR[EE];
__device__ float g_dinv[NN];
__device__ int   g_is64;   // 1 if edge_index is int64, 0 if int32

// ---------------- dtype detection ------------------------------------------
// Values are in [0, 50000). If buffer is int64 (little-endian), odd 32-bit
// words are all zero. If int32, odd words are random indices (P(0) = 2e-5 each).
__global__ void k_detect(const int* __restrict__ w) {
    int all0 = 1;
#pragma unroll
    for (int i = 1; i < 32; i += 2) all0 &= (w[i] == 0);
    g_is64 = all0;
}

__device__ __forceinline__ int load_idx(const void* ei, int pos) {
    if (g_is64) return (int)((const long long*)ei)[pos];
    return ((const int*)ei)[pos];
}

// ---------------- degree / CSR construction --------------------------------
__global__ void k_zero() {
    int i = blockIdx.x * blockDim.x + threadIdx.x;
    if (i < NN) g_cnt[i] = 0;
}

__global__ void k_count(const void* __restrict__ ei) {
    int e = blockIdx.x * blockDim.x + threadIdx.x;
    if (e < EE) {
        int t = load_idx(ei, EE + e);
        if ((unsigned)t < NN) atomicAdd(&g_cnt[t], 1);
    }
}

// single-block exclusive scan of g_cnt -> g_start
__global__ void k_scan() {
    const int T  = 1024;
    const int CH = (NN + T - 1) / T;  // 49
    int tid  = threadIdx.x;
    int base = tid * CH;
    int s = 0;
    for (int j = 0; j < CH; j++) {
        int i = base + j;
        if (i < NN) s += g_cnt[i];
    }
    __shared__ int ps[T];
    ps[tid] = s;
    __syncthreads();
    for (int off = 1; off < T; off <<= 1) {
        int v = (tid >= off) ? ps[tid - off] : 0;
        __syncthreads();
        ps[tid] += v;
        __syncthreads();
    }
    int run = ps[tid] - s;  // exclusive prefix at this thread's chunk start
    for (int j = 0; j < CH; j++) {
        int i = base + j;
        if (i < NN) { g_start[i] = run; run += g_cnt[i]; }
    }
    if (tid == 0) g_start[NN] = EE;
}

__global__ void k_prep() {
    int i = blockIdx.x * blockDim.x + threadIdx.x;
    if (i < NN) {
        g_cursor[i] = g_start[i];
        g_dinv[i]   = rsqrtf((float)(g_cnt[i] + 1));  // +1 self-loop, so >=1
    }
}

__global__ void k_fill(const void* __restrict__ ei) {
    int e = blockIdx.x * blockDim.x + threadIdx.x;
    if (e < EE) {
        int s = load_idx(ei, e);
        int t = load_idx(ei, EE + e);
        if ((unsigned)s < NN && (unsigned)t < NN) {
            int p = atomicAdd(&g_cursor[t], 1);
            g_srcCSR[p] = s;
        }
    }
}

// ---------------- GEMM: g_h[N,OUTC] = X[N,128] @ W[128,OUTC] + b ------------
// X is the external input when FROM_A=false, otherwise g_a (by symbol).
// 128-row x OUTC-col tile per block, 256 threads, 8x8 register blocking.
template <int OUTC, bool FROM_A>
__global__ void k_gemm(const float* __restrict__ Xext, const float* __restrict__ W,
                       const float* __restrict__ B) {
    const float* __restrict__ X = FROM_A ? (const float*)g_a : Xext;
    __shared__ float Xs[128][33];
    __shared__ float Ws[32][OUTC + 1];
    int tid = threadIdx.x;
    int tx  = tid & 15;   // col group
    int ty  = tid >> 4;   // row group (0..15)
    int row0 = blockIdx.x * 128;

    float acc[8][8];
#pragma unroll
    for (int i = 0; i < 8; i++)
#pragma unroll
        for (int j = 0; j < 8; j++) acc[i][j] = 0.f;

    for (int k0 = 0; k0 < DH; k0 += 32) {
#pragma unroll
        for (int l = tid; l < 1024; l += 256) {
            int r  = l >> 3;
            int c4 = l & 7;
            float4 v = make_float4(0.f, 0.f, 0.f, 0.f);
            int gr = row0 + r;
            if (gr < NN) v = *(const float4*)(X + (size_t)gr * DH + k0 + c4 * 4);
            Xs[r][c4 * 4 + 0] = v.x;
            Xs[r][c4 * 4 + 1] = v.y;
            Xs[r][c4 * 4 + 2] = v.z;
            Xs[r][c4 * 4 + 3] = v.w;
        }
        for (int l = tid; l < 32 * (OUTC / 4); l += 256) {
            int r  = l / (OUTC / 4);
            int c4 = l % (OUTC / 4);
            float4 v = *(const float4*)(W + (size_t)(k0 + r) * OUTC + c4 * 4);
            Ws[r][c4 * 4 + 0] = v.x;
            Ws[r][c4 * 4 + 1] = v.y;
            Ws[r][c4 * 4 + 2] = v.z;
            Ws[r][c4 * 4 + 3] = v.w;
        }
        __syncthreads();
#pragma unroll 8
        for (int kk = 0; kk < 32; kk++) {
            float xv[8], wv[8];
#pragma unroll
            for (int i = 0; i < 8; i++) xv[i] = Xs[ty + 16 * i][kk];
#pragma unroll
            for (int j = 0; j < 8; j++) {
                int c = tx + 16 * j;
                wv[j] = (c < OUTC) ? Ws[kk][c] : 0.f;
            }
#pragma unroll
            for (int i = 0; i < 8; i++)
#pragma unroll
                for (int j = 0; j < 8; j++) acc[i][j] += xv[i] * wv[j];
        }
        __syncthreads();
    }
#pragma unroll
    for (int i = 0; i < 8; i++) {
        int r = row0 + ty + 16 * i;
        if (r < NN) {
#pragma unroll
            for (int j = 0; j < 8; j++) {
                int c = tx + 16 * j;
                if (c < OUTC) g_h[(size_t)r * OUTC + c] = acc[i][j] + B[c];
            }
        }
    }
}

// -------- aggregation (gather over CSR) + fused BN + ReLU, d=128 ------------
// reads g_h, writes g_a. one warp per node, lane owns 4 contiguous features.
__global__ void k_agg128(const float* __restrict__ gg, const float* __restrict__ be,
                         const float* __restrict__ mm, const float* __restrict__ vv) {
    int w    = (blockIdx.x * blockDim.x + threadIdx.x) >> 5;
    int lane = threadIdx.x & 31;
    if (w >= NN) return;
    const float* __restrict__ h = (const float*)g_h;
    float di = g_dinv[w];
    float sn = di * di;  // self-loop norm
    float4 acc = *(const float4*)(h + (size_t)w * DH + lane * 4);
    acc.x *= sn; acc.y *= sn; acc.z *= sn; acc.w *= sn;
    int e0 = g_start[w], e1 = g_start[w + 1];
    for (int e = e0; e < e1; e++) {
        int s = g_srcCSR[e];
        float nw = g_dinv[s] * di;
        float4 v = *(const float4*)(h + (size_t)s * DH + lane * 4);
        acc.x += nw * v.x;
        acc.y += nw * v.y;
        acc.z += nw * v.z;
        acc.w += nw * v.w;
    }
    int c = lane * 4;
    float4 G  = *(const float4*)(gg + c);
    float4 BE = *(const float4*)(be + c);
    float4 M  = *(const float4*)(mm + c);
    float4 V  = *(const float4*)(vv + c);
    float r;
    r = (acc.x - M.x) * (G.x * rsqrtf(V.x + BN_EPS)) + BE.x; acc.x = fmaxf(r, 0.f);
    r = (acc.y - M.y) * (G.y * rsqrtf(V.y + BN_EPS)) + BE.y; acc.y = fmaxf(r, 0.f);
    r = (acc.z - M.z) * (G.z * rsqrtf(V.z + BN_EPS)) + BE.z; acc.z = fmaxf(r, 0.f);
    r = (acc.w - M.w) * (G.w * rsqrtf(V.w + BN_EPS)) + BE.w; acc.w = fmaxf(r, 0.f);
    *(float4*)(g_a + (size_t)w * DH + lane * 4) = acc;
}

// -------- last layer: aggregation (d=40) + fused log_softmax ----------------
// reads g_h (row stride DO), writes out. one warp per node.
__global__ void k_agg40(float* __restrict__ out) {
    int w    = (blockIdx.x * blockDim.x + threadIdx.x) >> 5;
    int lane = threadIdx.x & 31;
    if (w >= NN) return;
    const float* __restrict__ h = (const float*)g_h;
    float di = g_dinv[w];
    float sn = di * di;
    const float* hr = h + (size_t)w * DO;
    float a0 = sn * hr[lane];
    float a1 = (lane < 8) ? sn * hr[32 + lane] : 0.f;
    int e0 = g_start[w], e1 = g_start[w + 1];
    for (int e = e0; e < e1; e++) {
        int s = g_srcCSR[e];
        float nw = g_dinv[s] * di;
        const float* hs = h + (size_t)s * DO;
        a0 += nw * hs[lane];
        if (lane < 8) a1 += nw * hs[32 + lane];
    }
    // log_softmax over the 40 values held across the warp
    float mx = a0;
    if (lane < 8) mx = fmaxf(mx, a1);
#pragma unroll
    for (int off = 16; off > 0; off >>= 1)
        mx = fmaxf(mx, __shfl_xor_sync(0xffffffffu, mx, off));
    float se = expf(a0 - mx) + ((lane < 8) ? expf(a1 - mx) : 0.f);
#pragma unroll
    for (int off = 16; off > 0; off >>= 1)
        se += __shfl_xor_sync(0xffffffffu, se, off);
    float lse = mx + logf(se);
    out[(size_t)w * DO + lane] = a0 - lse;
    if (lane < 8) out[(size_t)w * DO + 32 + lane] = a1 - lse;
}

// ---------------- launch ----------------------------------------------------
extern "C" void kernel_launch(void* const* d_in, const int* in_sizes, int n_in,
                              void* d_out, int out_size) {
    const float* x  = (const float*)d_in[0];
    const void*  ei = d_in[1];                 // int32 or int64, detected on device
    const float* W0 = (const float*)d_in[2];
    const float* b0 = (const float*)d_in[3];
    const float* W1 = (const float*)d_in[4];
    const float* b1 = (const float*)d_in[5];
    const float* W2 = (const float*)d_in[6];
    const float* b2 = (const float*)d_in[7];
    const float* g0  = (const float*)d_in[8];
    const float* be0 = (const float*)d_in[9];
    const float* m0  = (const float*)d_in[10];
    const float* v0  = (const float*)d_in[11];
    const float* g1  = (const float*)d_in[12];
    const float* be1 = (const float*)d_in[13];
    const float* m1  = (const float*)d_in[14];
    const float* v1  = (const float*)d_in[15];
    float* out = (float*)d_out;

    const int TB = 256;
    int gbN = (NN + TB - 1) / TB;
    int gbE = (EE + TB - 1) / TB;
    int gbGemm = (NN + 127) / 128;                  // 391
    int gbWarp = (NN + (TB / 32) - 1) / (TB / 32);  // 6250

    // dtype detect + CSR build (reused by all 3 layers)
    k_detect<<<1, 1>>>((const int*)ei);
    k_zero<<<gbN, TB>>>();
    k_count<<<gbE, TB>>>(ei);
    k_scan<<<1, 1024>>>();
    k_prep<<<gbN, TB>>>();
    k_fill<<<gbE, TB>>>(ei);

    // layer 0: x -> g_h -> g_a
    k_gemm<DH, false><<<gbGemm, TB>>>(x, W0, b0);
    k_agg128<<<gbWarp, TB>>>(g0, be0, m0, v0);
    // layer 1: g_a -> g_h -> g_a
    k_gemm<DH, true><<<gbGemm, TB>>>(nullptr, W1, b1);
    k_agg128<<<gbWarp, TB>>>(g1, be1, m1, v1);
    // layer 2 + log_softmax: g_a -> g_h -> out
    k_gemm<DO, true><<<gbGemm, TB>>>(nullptr, W2, b2);
    k_agg40<<<gbWarp, TB>>>(out);
}

// round 4
// speedup vs baseline: 1.1157x; 1.1157x over previous
#include <cuda_runtime.h>

#define NN 50000
#define EE 600000
#define DH 128
#define DO 40
#define BN_EPS 1e-5f

// ---------------- scratch (device globals; referenced by symbol only) -------
__device__ __align__(16) float g_h[(size_t)NN * DH];   // GEMM out / agg in
__device__ __align__(16) float g_a[(size_t)NN * DH];   // agg out / GEMM in
__device__ int   g_cnt[NN];
__device__ int   g_start[NN + 1];
__device__ int   g_cursor[NN];
__device__ int   g_srcCSR[EE];
__device__ float g_dinv[NN];
__device__ int   g_is64;   // 1 if edge_index is int64, 0 if int32

// ---------------- dtype detection ------------------------------------------
// Values are in [0, 50000). If buffer is int64 (LE), odd 32-bit words are all 0.
__global__ void k_detect(const int* __restrict__ w) {
    int all0 = 1;
#pragma unroll
    for (int i = 1; i < 32; i += 2) all0 &= (w[i] == 0);
    g_is64 = all0;
}

__device__ __forceinline__ int load_idx(const void* ei, int pos) {
    if (g_is64) return (int)((const long long*)ei)[pos];
    return ((const int*)ei)[pos];
}

// ---------------- degree / CSR construction --------------------------------
__global__ void k_zero() {
    int i = blockIdx.x * blockDim.x + threadIdx.x;
    if (i < NN) g_cnt[i] = 0;
}

__global__ void k_count(const void* __restrict__ ei) {
    int e = blockIdx.x * blockDim.x + threadIdx.x;
    if (e < EE) {
        int t = load_idx(ei, EE + e);
        if ((unsigned)t < NN) atomicAdd(&g_cnt[t], 1);
    }
}

// Tiled warp-shuffle exclusive scan of g_cnt -> g_start, fused with
// cursor init and dinv computation (replaces old k_scan + k_prep).
__global__ void k_scan() {
    const int T = 1024;
    const int NT = (NN + T - 1) / T;  // 49 tiles
    int tid  = threadIdx.x;
    int lane = tid & 31;
    int wid  = tid >> 5;              // 0..31
    __shared__ int wsum[32];
    int carry = 0;
    for (int t = 0; t < NT; t++) {
        int i = t * T + tid;
        int c = (i < NN) ? g_cnt[i] : 0;
        // inclusive warp scan
        int v = c;
#pragma unroll
        for (int off = 1; off < 32; off <<= 1) {
            int n = __shfl_up_sync(0xffffffffu, v, off);
            if (lane >= off) v += n;
        }
        if (lane == 31) wsum[wid] = v;
        __syncthreads();
        if (wid == 0) {
            int s = wsum[lane];
#pragma unroll
            for (int off = 1; off < 32; off <<= 1) {
                int n = __shfl_up_sync(0xffffffffu, s, off);
                if (lane >= off) s += n;
            }
            wsum[lane] = s;
        }
        __syncthreads();
        int wexcl = (wid == 0) ? 0 : wsum[wid - 1];
        int excl  = carry + wexcl + v - c;
        if (i < NN) {
            g_start[i]  = excl;
            g_cursor[i] = excl;
            g_dinv[i]   = rsqrtf((float)(c + 1));  // +1 self-loop
        }
        carry += wsum[31];
        __syncthreads();  // protect wsum before next tile
    }
    if (tid == 0) g_start[NN] = EE;
}

__global__ void k_fill(const void* __restrict__ ei) {
    int e = blockIdx.x * blockDim.x + threadIdx.x;
    if (e < EE) {
        int s = load_idx(ei, e);
        int t = load_idx(ei, EE + e);
        if ((unsigned)s < NN && (unsigned)t < NN) {
            int p = atomicAdd(&g_cursor[t], 1);
            g_srcCSR[p] = s;
        }
    }
}

// ---------------- GEMM: g_h[N,OUTC] = X[N,128] @ W[128,OUTC] + b ------------
// 128-row tile per block, 256 threads, 8x8 register blocking.
// X tile stored k-major (transposed) in SMEM so the inner loop is
// 4x LDS.128 + 64 FFMA per k-step.
template <int OUTC, bool FROM_A>
__global__ void __launch_bounds__(256) k_gemm(const float* __restrict__ Xext,
                                              const float* __restrict__ W,
                                              const float* __restrict__ B) {
    const float* __restrict__ X = FROM_A ? (const float*)g_a : Xext;
    constexpr int WC = 132;            // padded row width (132*4 bytes = 33*16)
    constexpr bool HAS2 = (OUTC > 64); // second column group?
    __shared__ __align__(16) float Xs[32][WC];  // [k][row]
    __shared__ __align__(16) float Ws[32][WC];  // [k][col] (zero-padded)
    int tid = threadIdx.x;
    int tx  = tid & 15;   // col group (cols tx*4.. and 64+tx*4..)
    int ty  = tid >> 4;   // row group (rows ty*4.. and 64+ty*4..)
    int row0 = blockIdx.x * 128;

    float acc[8][8];
#pragma unroll
    for (int i = 0; i < 8; i++)
#pragma unroll
        for (int j = 0; j < 8; j++) acc[i][j] = 0.f;

    for (int k0 = 0; k0 < DH; k0 += 32) {
        // X tile: 128 rows x 32 k -> transposed store Xs[k][r]
#pragma unroll
        for (int l = tid; l < 1024; l += 256) {
            int r  = l >> 3;
            int c4 = l & 7;
            float4 v = make_float4(0.f, 0.f, 0.f, 0.f);
            int gr = row0 + r;
            if (gr < NN) v = *(const float4*)(X + (size_t)gr * DH + k0 + c4 * 4);
            Xs[c4 * 4 + 0][r] = v.x;
            Xs[c4 * 4 + 1][r] = v.y;
            Xs[c4 * 4 + 2][r] = v.z;
            Xs[c4 * 4 + 3][r] = v.w;
        }
        // W tile: 32 k x OUTC cols, rows zero-padded to WC
#pragma unroll
        for (int l = tid; l < 32 * (WC / 4); l += 256) {
            int r = l / (WC / 4);
            int c = (l % (WC / 4)) * 4;
            float4 v = make_float4(0.f, 0.f, 0.f, 0.f);
            if (c + 4 <= OUTC) v = *(const float4*)(W + (size_t)(k0 + r) * OUTC + c);
            *(float4*)&Ws[r][c] = v;
        }
        __syncthreads();
#pragma unroll
        for (int kk = 0; kk < 32; kk++) {
            float4 x0 = *(const float4*)&Xs[kk][ty * 4];
            float4 x1 = *(const float4*)&Xs[kk][64 + ty * 4];
            float4 w0 = *(const float4*)&Ws[kk][tx * 4];
            float4 w1 = *(const float4*)&Ws[kk][64 + tx * 4];
            float xv[8] = {x0.x, x0.y, x0.z, x0.w, x1.x, x1.y, x1.z, x1.w};
            float wv[8] = {w0.x, w0.y, w0.z, w0.w, w1.x, w1.y, w1.z, w1.w};
#pragma unroll
            for (int i = 0; i < 8; i++)
#pragma unroll
                for (int j = 0; j < 8; j++) acc[i][j] += xv[i] * wv[j];
        }
        __syncthreads();
    }

    // epilogue: fused bias, float4 stores
    float4 B0 = make_float4(0.f, 0.f, 0.f, 0.f), B1 = B0;
    if (tx * 4 + 4 <= OUTC) B0 = *(const float4*)(B + tx * 4);
    if (HAS2) B1 = *(const float4*)(B + 64 + tx * 4);
#pragma unroll
    for (int h = 0; h < 2; h++) {
#pragma unroll
        for (int ii = 0; ii < 3 + 1; ii++) {
            int r = row0 + h * 64 + ty * 4 + ii;
            if (r >= NN) continue;
            int xi = h * 4 + ii;
            if (tx * 4 + 4 <= OUTC) {
                float4 o;
                o.x = acc[xi][0] + B0.x;
                o.y = acc[xi][1] + B0.y;
                o.z = acc[xi][2] + B0.z;
                o.w = acc[xi][3] + B0.w;
                *(float4*)(g_h + (size_t)r * OUTC + tx * 4) = o;
            }
            if (HAS2) {
                float4 o;
                o.x = acc[xi][4] + B1.x;
                o.y = acc[xi][5] + B1.y;
                o.z = acc[xi][6] + B1.z;
                o.w = acc[xi][7] + B1.w;
                *(float4*)(g_h + (size_t)r * OUTC + 64 + tx * 4) = o;
            }
        }
    }
}

// -------- aggregation (gather over CSR) + fused BN + ReLU, d=128 ------------
// reads g_h, writes g_a. one warp per node, lane owns 4 contiguous features.
__global__ void k_agg128(const float* __restrict__ gg, const float* __restrict__ be,
                         const float* __restrict__ mm, const float* __restrict__ vv) {
    int w    = (blockIdx.x * blockDim.x + threadIdx.x) >> 5;
    int lane = threadIdx.x & 31;
    if (w >= NN) return;
    const float* __restrict__ h = (const float*)g_h;
    float di = g_dinv[w];
    float sn = di * di;  // self-loop norm
    float4 acc = *(const float4*)(h + (size_t)w * DH + lane * 4);
    acc.x *= sn; acc.y *= sn; acc.z *= sn; acc.w *= sn;
    int e0 = g_start[w], e1 = g_start[w + 1];
    for (int e = e0; e < e1; e++) {
        int s = g_srcCSR[e];
        float nw = g_dinv[s] * di;
        float4 v = *(const float4*)(h + (size_t)s * DH + lane * 4);
        acc.x += nw * v.x;
        acc.y += nw * v.y;
        acc.z += nw * v.z;
        acc.w += nw * v.w;
    }
    int c = lane * 4;
    float4 G  = *(const float4*)(gg + c);
    float4 BE = *(const float4*)(be + c);
    float4 M  = *(const float4*)(mm + c);
    float4 V  = *(const float4*)(vv + c);
    float r;
    r = (acc.x - M.x) * (G.x * rsqrtf(V.x + BN_EPS)) + BE.x; acc.x = fmaxf(r, 0.f);
    r = (acc.y - M.y) * (G.y * rsqrtf(V.y + BN_EPS)) + BE.y; acc.y = fmaxf(r, 0.f);
    r = (acc.z - M.z) * (G.z * rsqrtf(V.z + BN_EPS)) + BE.z; acc.z = fmaxf(r, 0.f);
    r = (acc.w - M.w) * (G.w * rsqrtf(V.w + BN_EPS)) + BE.w; acc.w = fmaxf(r, 0.f);
    *(float4*)(g_a + (size_t)w * DH + lane * 4) = acc;
}

// -------- last layer: aggregation (d=40) + fused log_softmax ----------------
__global__ void k_agg40(float* __restrict__ out) {
    int w    = (blockIdx.x * blockDim.x + threadIdx.x) >> 5;
    int lane = threadIdx.x & 31;
    if (w >= NN) return;
    const float* __restrict__ h = (const float*)g_h;
    float di = g_dinv[w];
    float sn = di * di;
    const float* hr = h + (size_t)w * DO;
    float a0 = sn * hr[lane];
    float a1 = (lane < 8) ? sn * hr[32 + lane] : 0.f;
    int e0 = g_start[w], e1 = g_start[w + 1];
    for (int e = e0; e < e1; e++) {
        int s = g_srcCSR[e];
        float nw = g_dinv[s] * di;
        const float* hs = h + (size_t)s * DO;
        a0 += nw * hs[lane];
        if (lane < 8) a1 += nw * hs[32 + lane];
    }
    float mx = a0;
    if (lane < 8) mx = fmaxf(mx, a1);
#pragma unroll
    for (int off = 16; off > 0; off >>= 1)
        mx = fmaxf(mx, __shfl_xor_sync(0xffffffffu, mx, off));
    float se = expf(a0 - mx) + ((lane < 8) ? expf(a1 - mx) : 0.f);
#pragma unroll
    for (int off = 16; off > 0; off >>= 1)
        se += __shfl_xor_sync(0xffffffffu, se, off);
    float lse = mx + logf(se);
    out[(size_t)w * DO + lane] = a0 - lse;
    if (lane < 8) out[(size_t)w * DO + 32 + lane] = a1 - lse;
}

// ---------------- launch ----------------------------------------------------
extern "C" void kernel_launch(void* const* d_in, const int* in_sizes, int n_in,
                              void* d_out, int out_size) {
    const float* x  = (const float*)d_in[0];
    const void*  ei = d_in[1];                 // int32 or int64, detected on device
    const float* W0 = (const float*)d_in[2];
    const float* b0 = (const float*)d_in[3];
    const float* W1 = (const float*)d_in[4];
    const float* b1 = (const float*)d_in[5];
    const float* W2 = (const float*)d_in[6];
    const float* b2 = (const float*)d_in[7];
    const float* g0  = (const float*)d_in[8];
    const float* be0 = (const float*)d_in[9];
    const float* m0  = (const float*)d_in[10];
    const float* v0  = (const float*)d_in[11];
    const float* g1  = (const float*)d_in[12];
    const float* be1 = (const float*)d_in[13];
    const float* m1  = (const float*)d_in[14];
    const float* v1  = (const float*)d_in[15];
    float* out = (float*)d_out;

    const int TB = 256;
    int gbN = (NN + TB - 1) / TB;
    int gbE = (EE + TB - 1) / TB;
    int gbGemm = (NN + 127) / 128;                  // 391
    int gbWarp = (NN + (TB / 32) - 1) / (TB / 32);  // 6250

    // dtype detect + CSR build (reused by all 3 layers)
    k_detect<<<1, 1>>>((const int*)ei);
    k_zero<<<gbN, TB>>>();
    k_count<<<gbE, TB>>>(ei);
    k_scan<<<1, 1024>>>();   // scan + cursor + dinv fused
    k_fill<<<gbE, TB>>>(ei);

    // layer 0: x -> g_h -> g_a
    k_gemm<DH, false><<<gbGemm, TB>>>(x, W0, b0);
    k_agg128<<<gbWarp, TB>>>(g0, be0, m0, v0);
    // layer 1: g_a -> g_h -> g_a
    k_gemm<DH, true><<<gbGemm, TB>>>(nullptr, W1, b1);
    k_agg128<<<gbWarp, TB>>>(g1, be1, m1, v1);
    // layer 2 + log_softmax: g_a -> g_h -> out
    k_gemm<DO, true><<<gbGemm, TB>>>(nullptr, W2, b2);
    k_agg40<<<gbWarp, TB>>>(out);
}

// round 5
// speedup vs baseline: 1.2680x; 1.1365x over previous
#include <cuda_runtime.h>

#define NN 50000
#define EE 600000
#define DH 128
#define DO 40
#define BN_EPS 1e-5f
#define SCAN_B 49   // ceil(NN/1024)

// ---------------- scratch (device globals; referenced by symbol only) -------
__device__ __align__(16) float g_h[(size_t)NN * DH];   // GEMM out / agg in
__device__ __align__(16) float g_a[(size_t)NN * DH];   // agg out / GEMM in
__device__ int   g_cnt[NN];
__device__ int   g_start[NN + 1];
__device__ int   g_cursor[NN];
__device__ int   g_srcCSR[EE];
__device__ float g_dinv[NN];
__device__ int   g_is64;            // 1 if edge_index is int64, 0 if int32
__device__ int   g_bsum[SCAN_B];    // per-block totals
__device__ int   g_boff[SCAN_B];    // exclusive block offsets

__device__ __forceinline__ int load_idx(const void* ei, int pos) {
    if (g_is64) return (int)((const long long*)ei)[pos];
    return ((const int*)ei)[pos];
}

// ---------------- zero counters + dtype detection (fused) -------------------
// Values in [0, 50000): if buffer is int64 (LE), odd 32-bit words are all 0.
__global__ void k_zero(const int* __restrict__ w) {
    int i = blockIdx.x * blockDim.x + threadIdx.x;
    if (i < NN) g_cnt[i] = 0;
    if (i == 0) {
        int all0 = 1;
#pragma unroll
        for (int k = 1; k < 32; k += 2) all0 &= (w[k] == 0);
        g_is64 = all0;
    }
}

__global__ void k_count(const void* __restrict__ ei) {
    int e = blockIdx.x * blockDim.x + threadIdx.x;
    if (e < EE) {
        int t = load_idx(ei, EE + e);
        if ((unsigned)t < NN) atomicAdd(&g_cnt[t], 1);
    }
}

// ---- multi-block scan: scan1 (block-local inclusive) ----------------------
__global__ void k_scan1() {
    __shared__ int wsum[32];
    int tid  = threadIdx.x;
    int lane = tid & 31;
    int wid  = tid >> 5;
    int i = blockIdx.x * 1024 + tid;
    int c = (i < NN) ? g_cnt[i] : 0;
    int v = c;
#pragma unroll
    for (int off = 1; off < 32; off <<= 1) {
        int n = __shfl_up_sync(0xffffffffu, v, off);
        if (lane >= off) v += n;
    }
    if (lane == 31) wsum[wid] = v;
    __syncthreads();
    if (wid == 0) {
        int s = wsum[lane];
#pragma unroll
        for (int off = 1; off < 32; off <<= 1) {
            int n = __shfl_up_sync(0xffffffffu, s, off);
            if (lane >= off) s += n;
        }
        wsum[lane] = s;
    }
    __syncthreads();
    int incl = ((wid == 0) ? 0 : wsum[wid - 1]) + v;
    if (i < NN) g_start[i] = incl;                    // temp: inclusive
    if (tid == 1023) g_bsum[blockIdx.x] = incl;       // block total
}

// ---- scan2: 1 warp, exclusive scan of 49 block totals ----------------------
__global__ void k_scan2() {
    int lane = threadIdx.x;
    int i0 = 2 * lane, i1 = 2 * lane + 1;
    int a = (i0 < SCAN_B) ? g_bsum[i0] : 0;
    int b = (i1 < SCAN_B) ? g_bsum[i1] : 0;
    int s = a + b, v = s;
#pragma unroll
    for (int off = 1; off < 32; off <<= 1) {
        int n = __shfl_up_sync(0xffffffffu, v, off);
        if (lane >= off) v += n;
    }
    int excl = v - s;
    if (i0 < SCAN_B) g_boff[i0] = excl;
    if (i1 < SCAN_B) g_boff[i1] = excl + a;
    if (lane == 31) g_start[NN] = EE;
}

// ---- scan3: finalize exclusive prefix + cursor + dinv ----------------------
__global__ void k_scan3() {
    int i = blockIdx.x * blockDim.x + threadIdx.x;
    if (i < NN) {
        int c    = g_cnt[i];
        int excl = g_start[i] - c + g_boff[i >> 10];
        g_start[i]  = excl;
        g_cursor[i] = excl;
        g_dinv[i]   = rsqrtf((float)(c + 1));  // +1 self-loop
    }
}

__global__ void k_fill(const void* __restrict__ ei) {
    int e = blockIdx.x * blockDim.x + threadIdx.x;
    if (e < EE) {
        int s = load_idx(ei, e);
        int t = load_idx(ei, EE + e);
        if ((unsigned)s < NN && (unsigned)t < NN) {
            int p = atomicAdd(&g_cursor[t], 1);
            g_srcCSR[p] = s;
        }
    }
}

// ---------------- GEMM: g_h[N,OUTC] = X[N,128] @ W[128,OUTC] + b ------------
// 128-row tile per block, 256 threads, 8x8 register blocking, k-major X tile.
template <int OUTC, bool FROM_A>
__global__ void __launch_bounds__(256) k_gemm(const float* __restrict__ Xext,
                                              const float* __restrict__ W,
                                              const float* __restrict__ B) {
    const float* __restrict__ X = FROM_A ? (const float*)g_a : Xext;
    constexpr int WC = 132;
    constexpr bool HAS2 = (OUTC > 64);
    __shared__ __align__(16) float Xs[32][WC];  // [k][row]
    __shared__ __align__(16) float Ws[32][WC];  // [k][col] (zero-padded)
    int tid = threadIdx.x;
    int tx  = tid & 15;
    int ty  = tid >> 4;
    int row0 = blockIdx.x * 128;

    float acc[8][8];
#pragma unroll
    for (int i = 0; i < 8; i++)
#pragma unroll
        for (int j = 0; j < 8; j++) acc[i][j] = 0.f;

    for (int k0 = 0; k0 < DH; k0 += 32) {
#pragma unroll
        for (int l = tid; l < 1024; l += 256) {
            int r  = l >> 3;
            int c4 = l & 7;
            float4 v = make_float4(0.f, 0.f, 0.f, 0.f);
            int gr = row0 + r;
            if (gr < NN) v = *(const float4*)(X + (size_t)gr * DH + k0 + c4 * 4);
            Xs[c4 * 4 + 0][r] = v.x;
            Xs[c4 * 4 + 1][r] = v.y;
            Xs[c4 * 4 + 2][r] = v.z;
            Xs[c4 * 4 + 3][r] = v.w;
        }
#pragma unroll
        for (int l = tid; l < 32 * (WC / 4); l += 256) {
            int r = l / (WC / 4);
            int c = (l % (WC / 4)) * 4;
            float4 v = make_float4(0.f, 0.f, 0.f, 0.f);
            if (c + 4 <= OUTC) v = *(const float4*)(W + (size_t)(k0 + r) * OUTC + c);
            *(float4*)&Ws[r][c] = v;
        }
        __syncthreads();
#pragma unroll
        for (int kk = 0; kk < 32; kk++) {
            float4 x0 = *(const float4*)&Xs[kk][ty * 4];
            float4 x1 = *(const float4*)&Xs[kk][64 + ty * 4];
            float4 w0 = *(const float4*)&Ws[kk][tx * 4];
            float4 w1 = *(const float4*)&Ws[kk][64 + tx * 4];
            float xv[8] = {x0.x, x0.y, x0.z, x0.w, x1.x, x1.y, x1.z, x1.w};
            float wv[8] = {w0.x, w0.y, w0.z, w0.w, w1.x, w1.y, w1.z, w1.w};
#pragma unroll
            for (int i = 0; i < 8; i++)
#pragma unroll
                for (int j = 0; j < 8; j++) acc[i][j] += xv[i] * wv[j];
        }
        __syncthreads();
    }

    float4 B0 = make_float4(0.f, 0.f, 0.f, 0.f), B1 = B0;
    if (tx * 4 + 4 <= OUTC) B0 = *(const float4*)(B + tx * 4);
    if (HAS2) B1 = *(const float4*)(B + 64 + tx * 4);
#pragma unroll
    for (int h = 0; h < 2; h++) {
#pragma unroll
        for (int ii = 0; ii < 4; ii++) {
            int r = row0 + h * 64 + ty * 4 + ii;
            if (r >= NN) continue;
            int xi = h * 4 + ii;
            if (tx * 4 + 4 <= OUTC) {
                float4 o;
                o.x = acc[xi][0] + B0.x;
                o.y = acc[xi][1] + B0.y;
                o.z = acc[xi][2] + B0.z;
                o.w = acc[xi][3] + B0.w;
                *(float4*)(g_h + (size_t)r * OUTC + tx * 4) = o;
            }
            if (HAS2) {
                float4 o;
                o.x = acc[xi][4] + B1.x;
                o.y = acc[xi][5] + B1.y;
                o.z = acc[xi][6] + B1.z;
                o.w = acc[xi][7] + B1.w;
                *(float4*)(g_h + (size_t)r * OUTC + 64 + tx * 4) = o;
            }
        }
    }
}

// -------- aggregation (gather over CSR) + fused BN + ReLU, d=128 ------------
__global__ void k_agg128(const float* __restrict__ gg, const float* __restrict__ be,
                         const float* __restrict__ mm, const float* __restrict__ vv) {
    int w    = (blockIdx.x * blockDim.x + threadIdx.x) >> 5;
    int lane = threadIdx.x & 31;
    if (w >= NN) return;
    const float* __restrict__ h = (const float*)g_h;
    float di = g_dinv[w];
    float sn = di * di;
    float4 acc = *(const float4*)(h + (size_t)w * DH + lane * 4);
    acc.x *= sn; acc.y *= sn; acc.z *= sn; acc.w *= sn;
    int e0 = g_start[w], e1 = g_start[w + 1];
    for (int e = e0; e < e1; e++) {
        int s = g_srcCSR[e];
        float nw = g_dinv[s] * di;
        float4 v = *(const float4*)(h + (size_t)s * DH + lane * 4);
        acc.x += nw * v.x;
        acc.y += nw * v.y;
        acc.z += nw * v.z;
        acc.w += nw * v.w;
    }
    int c = lane * 4;
    float4 G  = *(const float4*)(gg + c);
    float4 BE = *(const float4*)(be + c);
    float4 M  = *(const float4*)(mm + c);
    float4 V  = *(const float4*)(vv + c);
    float r;
    r = (acc.x - M.x) * (G.x * rsqrtf(V.x + BN_EPS)) + BE.x; acc.x = fmaxf(r, 0.f);
    r = (acc.y - M.y) * (G.y * rsqrtf(V.y + BN_EPS)) + BE.y; acc.y = fmaxf(r, 0.f);
    r = (acc.z - M.z) * (G.z * rsqrtf(V.z + BN_EPS)) + BE.z; acc.z = fmaxf(r, 0.f);
    r = (acc.w - M.w) * (G.w * rsqrtf(V.w + BN_EPS)) + BE.w; acc.w = fmaxf(r, 0.f);
    *(float4*)(g_a + (size_t)w * DH + lane * 4) = acc;
}

// -------- last layer: aggregation (d=40) + fused log_softmax ----------------
__global__ void k_agg40(float* __restrict__ out) {
    int w    = (blockIdx.x * blockDim.x + threadIdx.x) >> 5;
    int lane = threadIdx.x & 31;
    if (w >= NN) return;
    const float* __restrict__ h = (const float*)g_h;
    float di = g_dinv[w];
    float sn = di * di;
    const float* hr = h + (size_t)w * DO;
    float a0 = sn * hr[lane];
    float a1 = (lane < 8) ? sn * hr[32 + lane] : 0.f;
    int e0 = g_start[w], e1 = g_start[w + 1];
    for (int e = e0; e < e1; e++) {
        int s = g_srcCSR[e];
        float nw = g_dinv[s] * di;
        const float* hs = h + (size_t)s * DO;
        a0 += nw * hs[lane];
        if (lane < 8) a1 += nw * hs[32 + lane];
    }
    float mx = a0;
    if (lane < 8) mx = fmaxf(mx, a1);
#pragma unroll
    for (int off = 16; off > 0; off >>= 1)
        mx = fmaxf(mx, __shfl_xor_sync(0xffffffffu, mx, off));
    float se = expf(a0 - mx) + ((lane < 8) ? expf(a1 - mx) : 0.f);
#pragma unroll
    for (int off = 16; off > 0; off >>= 1)
        se += __shfl_xor_sync(0xffffffffu, se, off);
    float lse = mx + logf(se);
    out[(size_t)w * DO + lane] = a0 - lse;
    if (lane < 8) out[(size_t)w * DO + 32 + lane] = a1 - lse;
}

// ---------------- launch ----------------------------------------------------
extern "C" void kernel_launch(void* const* d_in, const int* in_sizes, int n_in,
                              void* d_out, int out_size) {
    const float* x  = (const float*)d_in[0];
    const void*  ei = d_in[1];
    const float* W0 = (const float*)d_in[2];
    const float* b0 = (const float*)d_in[3];
    const float* W1 = (const float*)d_in[4];
    const float* b1 = (const float*)d_in[5];
    const float* W2 = (const float*)d_in[6];
    const float* b2 = (const float*)d_in[7];
    const float* g0  = (const float*)d_in[8];
    const float* be0 = (const float*)d_in[9];
    const float* m0  = (const float*)d_in[10];
    const float* v0  = (const float*)d_in[11];
    const float* g1  = (const float*)d_in[12];
    const float* be1 = (const float*)d_in[13];
    const float* m1  = (const float*)d_in[14];
    const float* v1  = (const float*)d_in[15];
    float* out = (float*)d_out;

    const int TB = 256;
    int gbN = (NN + TB - 1) / TB;
    int gbE = (EE + TB - 1) / TB;
    int gbGemm = (NN + 127) / 128;
    int gbWarp = (NN + (TB / 32) - 1) / (TB / 32);

    // CSR build (multi-block scan; reused by all 3 layers)
    k_zero<<<gbN, TB>>>((const int*)ei);
    k_count<<<gbE, TB>>>(ei);
    k_scan1<<<SCAN_B, 1024>>>();
    k_scan2<<<1, 32>>>();
    k_scan3<<<gbN, TB>>>();
    k_fill<<<gbE, TB>>>(ei);

    // layer 0: x -> g_h -> g_a
    k_gemm<DH, false><<<gbGemm, TB>>>(x, W0, b0);
    k_agg128<<<gbWarp, TB>>>(g0, be0, m0, v0);
    // layer 1: g_a -> g_h -> g_a
    k_gemm<DH, true><<<gbGemm, TB>>>(nullptr, W1, b1);
    k_agg128<<<gbWarp, TB>>>(g1, be1, m1, v1);
    // layer 2 + log_softmax: g_a -> g_h -> out
    k_gemm<DO, true><<<gbGemm, TB>>>(nullptr, W2, b2);
    k_agg40<<<gbWarp, TB>>>(out);
}

// round 6
// speedup vs baseline: 1.5387x; 1.2135x over previous
#include <cuda_runtime.h>

#define NN 50000
#define EE 600000
#define DH 128
#define DO 40
#define BN_EPS 1e-5f
#define SCAN_B 49   // ceil(NN/1024)

// ---------------- scratch (device globals; referenced by symbol only) -------
__device__ __align__(16) float g_h[(size_t)NN * DH];   // GEMM out / agg in
__device__ __align__(16) float g_a[(size_t)NN * DH];   // agg out / GEMM in
__device__ int   g_cnt[NN];
__device__ int   g_start[NN + 1];
__device__ int   g_cursor[NN];
__device__ int   g_srcCSR[EE];
__device__ float g_dinv[NN];
__device__ int   g_is64;            // 1 if edge_index is int64, 0 if int32
__device__ int   g_bsum[SCAN_B];    // per-tile (1024) totals

__device__ __forceinline__ int load_idx(const void* ei, int pos) {
    if (g_is64) return (int)((const long long*)ei)[pos];
    return ((const int*)ei)[pos];
}

// ---------------- zero counters + dtype detection (fused) -------------------
__global__ void k_zero(const int* __restrict__ w) {
    int i = blockIdx.x * blockDim.x + threadIdx.x;
    if (i < NN) g_cnt[i] = 0;
    if (i == 0) {
        int all0 = 1;
#pragma unroll
        for (int k = 1; k < 32; k += 2) all0 &= (w[k] == 0);
        g_is64 = all0;
    }
}

__global__ void k_count(const void* __restrict__ ei) {
    int e = blockIdx.x * blockDim.x + threadIdx.x;
    if (e < EE) {
        int t = load_idx(ei, EE + e);
        if ((unsigned)t < NN) atomicAdd(&g_cnt[t], 1);
    }
}

// ---- scan1: block-local inclusive scan over 1024-tiles ---------------------
__global__ void k_scan1() {
    __shared__ int wsum[32];
    int tid  = threadIdx.x;
    int lane = tid & 31;
    int wid  = tid >> 5;
    int i = blockIdx.x * 1024 + tid;
    int c = (i < NN) ? g_cnt[i] : 0;
    int v = c;
#pragma unroll
    for (int off = 1; off < 32; off <<= 1) {
        int n = __shfl_up_sync(0xffffffffu, v, off);
        if (lane >= off) v += n;
    }
    if (lane == 31) wsum[wid] = v;
    __syncthreads();
    if (wid == 0) {
        int s = wsum[lane];
#pragma unroll
        for (int off = 1; off < 32; off <<= 1) {
            int n = __shfl_up_sync(0xffffffffu, s, off);
            if (lane >= off) s += n;
        }
        wsum[lane] = s;
    }
    __syncthreads();
    int incl = ((wid == 0) ? 0 : wsum[wid - 1]) + v;
    if (i < NN) g_start[i] = incl;                    // temp: inclusive in tile
    if (tid == 1023) g_bsum[blockIdx.x] = incl;       // tile total
}

// ---- scan23: tile offset (warp-reduce of g_bsum) + finalize -----------------
// each 256-thread block covers indices [b*256, b*256+256) -> one tile (b>>2)
__global__ void k_scan23() {
    __shared__ int s_off;
    int tid = threadIdx.x;
    int bq  = blockIdx.x >> 2;   // tile index of this block
    if (tid < 32) {
        int lane = tid;
        int v = (lane < bq) ? g_bsum[lane] : 0;
        if (lane + 32 < bq) v += g_bsum[lane + 32];
#pragma unroll
        for (int off = 16; off > 0; off >>= 1)
            v += __shfl_xor_sync(0xffffffffu, v, off);
        if (lane == 0) s_off = v;
    }
    __syncthreads();
    int boff = s_off;
    int i = blockIdx.x * blockDim.x + tid;
    if (i < NN) {
        int c    = g_cnt[i];
        int excl = g_start[i] - c + boff;
        g_start[i]  = excl;
        g_cursor[i] = excl;
        g_dinv[i]   = rsqrtf((float)(c + 1));  // +1 self-loop
    }
    if (blockIdx.x == 0 && tid == 0) g_start[NN] = EE;
}

__global__ void k_fill(const void* __restrict__ ei) {
    int e = blockIdx.x * blockDim.x + threadIdx.x;
    if (e < EE) {
        int s = load_idx(ei, e);
        int t = load_idx(ei, EE + e);
        if ((unsigned)s < NN && (unsigned)t < NN) {
            int p = atomicAdd(&g_cursor[t], 1);
            g_srcCSR[p] = s;
        }
    }
}

// ---------------- GEMM (OUTC=128): 128-row tile, 256 thr, 8x8 blocking ------
template <bool FROM_A>
__global__ void __launch_bounds__(256) k_gemm(const float* __restrict__ Xext,
                                              const float* __restrict__ W,
                                              const float* __restrict__ B) {
    const float* __restrict__ X = FROM_A ? (const float*)g_a : Xext;
    constexpr int WC = 132;
    __shared__ __align__(16) float Xs[32][WC];  // [k][row]
    __shared__ __align__(16) float Ws[32][WC];  // [k][col]
    int tid = threadIdx.x;
    int tx  = tid & 15;
    int ty  = tid >> 4;
    int row0 = blockIdx.x * 128;

    float acc[8][8];
#pragma unroll
    for (int i = 0; i < 8; i++)
#pragma unroll
        for (int j = 0; j < 8; j++) acc[i][j] = 0.f;

    for (int k0 = 0; k0 < DH; k0 += 32) {
#pragma unroll
        for (int l = tid; l < 1024; l += 256) {
            int r  = l >> 3;
            int c4 = l & 7;
            float4 v = make_float4(0.f, 0.f, 0.f, 0.f);
            int gr = row0 + r;
            if (gr < NN) v = *(const float4*)(X + (size_t)gr * DH + k0 + c4 * 4);
            Xs[c4 * 4 + 0][r] = v.x;
            Xs[c4 * 4 + 1][r] = v.y;
            Xs[c4 * 4 + 2][r] = v.z;
            Xs[c4 * 4 + 3][r] = v.w;
        }
#pragma unroll
        for (int l = tid; l < 1024; l += 256) {
            int r = l >> 5;
            int c = (l & 31) * 4;
            float4 v = *(const float4*)(W + (size_t)(k0 + r) * DH + c);
            *(float4*)&Ws[r][c] = v;
        }
        __syncthreads();
#pragma unroll
        for (int kk = 0; kk < 32; kk++) {
            float4 x0 = *(const float4*)&Xs[kk][ty * 4];
            float4 x1 = *(const float4*)&Xs[kk][64 + ty * 4];
            float4 w0 = *(const float4*)&Ws[kk][tx * 4];
            float4 w1 = *(const float4*)&Ws[kk][64 + tx * 4];
            float xv[8] = {x0.x, x0.y, x0.z, x0.w, x1.x, x1.y, x1.z, x1.w};
            float wv[8] = {w0.x, w0.y, w0.z, w0.w, w1.x, w1.y, w1.z, w1.w};
#pragma unroll
            for (int i = 0; i < 8; i++)
#pragma unroll
                for (int j = 0; j < 8; j++) acc[i][j] += xv[i] * wv[j];
        }
        __syncthreads();
    }

    float4 B0 = *(const float4*)(B + tx * 4);
    float4 B1 = *(const float4*)(B + 64 + tx * 4);
#pragma unroll
    for (int h = 0; h < 2; h++) {
#pragma unroll
        for (int ii = 0; ii < 4; ii++) {
            int r = row0 + h * 64 + ty * 4 + ii;
            if (r >= NN) continue;
            int xi = h * 4 + ii;
            float4 o;
            o.x = acc[xi][0] + B0.x;
            o.y = acc[xi][1] + B0.y;
            o.z = acc[xi][2] + B0.z;
            o.w = acc[xi][3] + B0.w;
            *(float4*)(g_h + (size_t)r * DH + tx * 4) = o;
            o.x = acc[xi][4] + B1.x;
            o.y = acc[xi][5] + B1.y;
            o.z = acc[xi][6] + B1.z;
            o.w = acc[xi][7] + B1.w;
            *(float4*)(g_h + (size_t)r * DH + 64 + tx * 4) = o;
        }
    }
}

// ---------------- GEMM (OUTC=40): 128-row tile, 160 thr, 8x4 blocking -------
__global__ void __launch_bounds__(160) k_gemm40(const float* __restrict__ W,
                                                const float* __restrict__ B) {
    const float* __restrict__ X = (const float*)g_a;
    constexpr int WC = 44;             // padded 40-col row
    __shared__ __align__(16) float Xs[32][132];  // [k][row]
    __shared__ __align__(16) float Ws[32][WC];   // [k][col]
    int tid = threadIdx.x;
    int tx  = tid % 10;   // col group: cols tx*4..tx*4+3
    int ty  = tid / 10;   // row group: rows ty*8..ty*8+7
    int row0 = blockIdx.x * 128;

    float acc[8][4];
#pragma unroll
    for (int i = 0; i < 8; i++)
#pragma unroll
        for (int j = 0; j < 4; j++) acc[i][j] = 0.f;

    for (int k0 = 0; k0 < DH; k0 += 32) {
        for (int l = tid; l < 1024; l += 160) {
            int r  = l >> 3;
            int c4 = l & 7;
            float4 v = make_float4(0.f, 0.f, 0.f, 0.f);
            int gr = row0 + r;
            if (gr < NN) v = *(const float4*)(X + (size_t)gr * DH + k0 + c4 * 4);
            Xs[c4 * 4 + 0][r] = v.x;
            Xs[c4 * 4 + 1][r] = v.y;
            Xs[c4 * 4 + 2][r] = v.z;
            Xs[c4 * 4 + 3][r] = v.w;
        }
        for (int l = tid; l < 320; l += 160) {   // 32 k x 10 col-groups
            int r = l / 10;
            int c = (l % 10) * 4;
            float4 v = *(const float4*)(W + (size_t)(k0 + r) * DO + c);
            *(float4*)&Ws[r][c] = v;
        }
        __syncthreads();
#pragma unroll
        for (int kk = 0; kk < 32; kk++) {
            float4 x0 = *(const float4*)&Xs[kk][ty * 8];
            float4 x1 = *(const float4*)&Xs[kk][ty * 8 + 4];
            float4 w0 = *(const float4*)&Ws[kk][tx * 4];
            float xv[8] = {x0.x, x0.y, x0.z, x0.w, x1.x, x1.y, x1.z, x1.w};
            float wv[4] = {w0.x, w0.y, w0.z, w0.w};
#pragma unroll
            for (int i = 0; i < 8; i++)
#pragma unroll
                for (int j = 0; j < 4; j++) acc[i][j] += xv[i] * wv[j];
        }
        __syncthreads();
    }

    float4 B0 = *(const float4*)(B + tx * 4);
#pragma unroll
    for (int i = 0; i < 8; i++) {
        int r = row0 + ty * 8 + i;
        if (r >= NN) continue;
        float4 o;
        o.x = acc[i][0] + B0.x;
        o.y = acc[i][1] + B0.y;
        o.z = acc[i][2] + B0.z;
        o.w = acc[i][3] + B0.w;
        *(float4*)(g_h + (size_t)r * DO + tx * 4) = o;
    }
}

// -------- aggregation (gather over CSR) + fused BN + ReLU, d=128 ------------
__global__ void k_agg128(const float* __restrict__ gg, const float* __restrict__ be,
                         const float* __restrict__ mm, const float* __restrict__ vv) {
    int w    = (blockIdx.x * blockDim.x + threadIdx.x) >> 5;
    int lane = threadIdx.x & 31;
    if (w >= NN) return;
    const float* __restrict__ h = (const float*)g_h;
    float di = g_dinv[w];
    float sn = di * di;
    float4 acc = *(const float4*)(h + (size_t)w * DH + lane * 4);
    acc.x *= sn; acc.y *= sn; acc.z *= sn; acc.w *= sn;
    int e0 = g_start[w], e1 = g_start[w + 1];
    for (int e = e0; e < e1; e++) {
        int s = g_srcCSR[e];
        float nw = g_dinv[s] * di;
        float4 v = *(const float4*)(h + (size_t)s * DH + lane * 4);
        acc.x += nw * v.x;
        acc.y += nw * v.y;
        acc.z += nw * v.z;
        acc.w += nw * v.w;
    }
    int c = lane * 4;
    float4 G  = *(const float4*)(gg + c);
    float4 BE = *(const float4*)(be + c);
    float4 M  = *(const float4*)(mm + c);
    float4 V  = *(const float4*)(vv + c);
    float r;
    r = (acc.x - M.x) * (G.x * rsqrtf(V.x + BN_EPS)) + BE.x; acc.x = fmaxf(r, 0.f);
    r = (acc.y - M.y) * (G.y * rsqrtf(V.y + BN_EPS)) + BE.y; acc.y = fmaxf(r, 0.f);
    r = (acc.z - M.z) * (G.z * rsqrtf(V.z + BN_EPS)) + BE.z; acc.z = fmaxf(r, 0.f);
    r = (acc.w - M.w) * (G.w * rsqrtf(V.w + BN_EPS)) + BE.w; acc.w = fmaxf(r, 0.f);
    *(float4*)(g_a + (size_t)w * DH + lane * 4) = acc;
}

// -------- last layer: aggregation (d=40) + fused log_softmax ----------------
__global__ void k_agg40(float* __restrict__ out) {
    int w    = (blockIdx.x * blockDim.x + threadIdx.x) >> 5;
    int lane = threadIdx.x & 31;
    if (w >= NN) return;
    const float* __restrict__ h = (const float*)g_h;
    float di = g_dinv[w];
    float sn = di * di;
    const float* hr = h + (size_t)w * DO;
    float a0 = sn * hr[lane];
    float a1 = (lane < 8) ? sn * hr[32 + lane] : 0.f;
    int e0 = g_start[w], e1 = g_start[w + 1];
    for (int e = e0; e < e1; e++) {
        int s = g_srcCSR[e];
        float nw = g_dinv[s] * di;
        const float* hs = h + (size_t)s * DO;
        a0 += nw * hs[lane];
        if (lane < 8) a1 += nw * hs[32 + lane];
    }
    float mx = a0;
    if (lane < 8) mx = fmaxf(mx, a1);
#pragma unroll
    for (int off = 16; off > 0; off >>= 1)
        mx = fmaxf(mx, __shfl_xor_sync(0xffffffffu, mx, off));
    float se = expf(a0 - mx) + ((lane < 8) ? expf(a1 - mx) : 0.f);
#pragma unroll
    for (int off = 16; off > 0; off >>= 1)
        se += __shfl_xor_sync(0xffffffffu, se, off);
    float lse = mx + logf(se);
    out[(size_t)w * DO + lane] = a0 - lse;
    if (lane < 8) out[(size_t)w * DO + 32 + lane] = a1 - lse;
}

// ---------------- launch ----------------------------------------------------
extern "C" void kernel_launch(void* const* d_in, const int* in_sizes, int n_in,
                              void* d_out, int out_size) {
    const float* x  = (const float*)d_in[0];
    const void*  ei = d_in[1];
    const float* W0 = (const float*)d_in[2];
    const float* b0 = (const float*)d_in[3];
    const float* W1 = (const float*)d_in[4];
    const float* b1 = (const float*)d_in[5];
    const float* W2 = (const float*)d_in[6];
    const float* b2 = (const float*)d_in[7];
    const float* g0  = (const float*)d_in[8];
    const float* be0 = (const float*)d_in[9];
    const float* m0  = (const float*)d_in[10];
    const float* v0  = (const float*)d_in[11];
    const float* g1  = (const float*)d_in[12];
    const float* be1 = (const float*)d_in[13];
    const float* m1  = (const float*)d_in[14];
    const float* v1  = (const float*)d_in[15];
    float* out = (float*)d_out;

    const int TB = 256;
    int gbN = (NN + TB - 1) / TB;
    int gbE = (EE + TB - 1) / TB;
    int gbGemm = (NN + 127) / 128;
    int gbWarp = (NN + (TB / 32) - 1) / (TB / 32);

    // Fork a side stream: CSR build runs concurrently with GEMM layer 0.
    // (handles created per-call and leaked on purpose: destroying mid-capture
    //  is the only unsafe op; handles are host-side, no device memory.)
    cudaStream_t s2;
    cudaStreamCreate(&s2);
    cudaEvent_t eFork, eJoin;
    cudaEventCreateWithFlags(&eFork, cudaEventDisableTiming);
    cudaEventCreateWithFlags(&eJoin, cudaEventDisableTiming);

    cudaEventRecord(eFork, 0);
    cudaStreamWaitEvent(s2, eFork, 0);

    // CSR build on side stream
    k_zero<<<gbN, TB, 0, s2>>>((const int*)ei);
    k_count<<<gbE, TB, 0, s2>>>(ei);
    k_scan1<<<SCAN_B, 1024, 0, s2>>>();
    k_scan23<<<gbN, TB, 0, s2>>>();
    k_fill<<<gbE, TB, 0, s2>>>(ei);
    cudaEventRecord(eJoin, s2);

    // GEMM layer 0 on main stream, concurrent with CSR build
    k_gemm<false><<<gbGemm, TB>>>(x, W0, b0);
    cudaStreamWaitEvent(0, eJoin, 0);   // join: agg needs CSR + gemm0

    k_agg128<<<gbWarp, TB>>>(g0, be0, m0, v0);
    k_gemm<true><<<gbGemm, TB>>>(nullptr, W1, b1);
    k_agg128<<<gbWarp, TB>>>(g1, be1, m1, v1);
    k_gemm40<<<gbGemm, 160>>>(W2, b2);
    k_agg40<<<gbWarp, TB>>>(out);
}